// round 3
// baseline (speedup 1.0000x reference)
#include <cuda_runtime.h>
#include <math.h>
#include <stdint.h>

// Problem constants
#define BATCH 128
#define SEQ   512
#define DIM   768
#define NCLS  9
#define ROWS  (BATCH * SEQ)   // 65536
#define D4    (DIM / 4)       // 192

// per-batch log-likelihood scratch
__device__ float g_llh[BATCH];

// ---------------------------------------------------------------------------
// Kernel 1: logits = features @ W^T + b
// Block: 256 threads (8 warps). Warp handles 8 rows: 4 groups (2 rows each),
// 8 lanes per group split D into float4 chunks. W cached in smem; LDS
// addresses identical across the 4 groups -> broadcast (no extra smem BW).
// ---------------------------------------------------------------------------
__global__ __launch_bounds__(256) void gemm_kernel(
    const float4* __restrict__ feat4,
    const float*  __restrict__ W,
    const float*  __restrict__ bias,
    float*        __restrict__ out_logits)
{
    __shared__ float4 Ws4[NCLS * D4];  // 27648 B
    __shared__ float  bS[NCLS];

    const float4* W4 = reinterpret_cast<const float4*>(W);
    for (int i = threadIdx.x; i < NCLS * D4; i += 256) Ws4[i] = W4[i];
    if (threadIdx.x < NCLS) bS[threadIdx.x] = bias[threadIdx.x];
    __syncthreads();

    const int warp = threadIdx.x >> 5;
    const int lane = threadIdx.x & 31;
    const int li   = lane & 7;   // d-chunk within group
    const int g    = lane >> 3;  // group (0..3), 2 rows each

    const int rowa = blockIdx.x * 64 + warp * 8 + g * 2;
    const int rowb = rowa + 1;

    float acc[NCLS][2];
#pragma unroll
    for (int n = 0; n < NCLS; ++n) { acc[n][0] = 0.f; acc[n][1] = 0.f; }

    const float4* fa = feat4 + (size_t)rowa * D4;
    const float4* fb = feat4 + (size_t)rowb * D4;

#pragma unroll 4
    for (int k = 0; k < 24; ++k) {
        const int idx = k * 8 + li;          // 0..191
        const float4 a  = fa[idx];
        const float4 bv = fb[idx];
#pragma unroll
        for (int n = 0; n < NCLS; ++n) {
            const float4 w = Ws4[n * D4 + idx];
            acc[n][0] = fmaf(a.x,  w.x, fmaf(a.y,  w.y, fmaf(a.z,  w.z, fmaf(a.w,  w.w, acc[n][0]))));
            acc[n][1] = fmaf(bv.x, w.x, fmaf(bv.y, w.y, fmaf(bv.z, w.z, fmaf(bv.w, w.w, acc[n][1]))));
        }
    }

    // reduce over the 8 lanes of each group
#pragma unroll
    for (int n = 0; n < NCLS; ++n) {
#pragma unroll
        for (int off = 4; off; off >>= 1) {
            acc[n][0] += __shfl_down_sync(0xffffffffu, acc[n][0], off, 8);
            acc[n][1] += __shfl_down_sync(0xffffffffu, acc[n][1], off, 8);
        }
    }

    if (li == 0) {
#pragma unroll
        for (int n = 0; n < NCLS; ++n) {
            out_logits[(size_t)rowa * NCLS + n] = acc[n][0] + bS[n];
            out_logits[(size_t)rowb * NCLS + n] = acc[n][1] + bS[n];
        }
    }
}

// ---------------------------------------------------------------------------
// Kernel 2: per-batch CRF forward (denominator) + gold-path score (numerator).
// One block of 128 threads per batch element.
//   Phase 1 (all): stage logits, E=exp(logits), tags, mask into smem.
//   Phase 2: warp 0 runs the linear-space forward recursion (no MUFU in the
//            serial loop); warp 1 computes the numerator in parallel.
// Mask is int32 (harness promotes bool -> int32).
// ---------------------------------------------------------------------------
__global__ __launch_bounds__(128) void crf_kernel(
    const float* __restrict__ logits,
    const int*   __restrict__ labels,
    const int*   __restrict__ mask,
    const float* __restrict__ start_t,
    const float* __restrict__ end_t,
    const float* __restrict__ trans)
{
    __shared__ float LG[SEQ * NCLS];
    __shared__ float EE[SEQ * NCLS];
    __shared__ int   tagS[SEQ];
    __shared__ int   mS[SEQ];
    __shared__ float trS[NCLS * NCLS];
    __shared__ float stS[NCLS], enS[NCLS];
    __shared__ float num_sh, den_sh;

    const int b   = blockIdx.x;
    const int tid = threadIdx.x;
    const float* lgb = logits + (size_t)b * SEQ * NCLS;

    for (int i = tid; i < SEQ * NCLS; i += 128) {
        const float v = lgb[i];
        LG[i] = v;
        EE[i] = expf(v);
    }
    for (int i = tid; i < SEQ; i += 128) {
        const int lab = labels[(size_t)b * SEQ + i];
        tagS[i] = (lab == -100) ? 0 : lab;
        mS[i]   = (mask[(size_t)b * SEQ + i] != 0) ? 1 : 0;
    }
    if (tid < NCLS * NCLS) trS[tid] = trans[tid];
    if (tid < NCLS) { stS[tid] = start_t[tid]; enS[tid] = end_t[tid]; }
    __syncthreads();

    const int warp = tid >> 5;
    const int lane = tid & 31;

    if (warp == 0) {
        const int j = (lane < NCLS) ? lane : (NCLS - 1);
        float trM[NCLS];
#pragma unroll
        for (int i = 0; i < NCLS; ++i) trM[i] = expf(trS[i * NCLS + j]);

        float p = (lane < NCLS) ? expf(stS[j] + LG[j]) : 0.f;  // p = exp(alpha0)
        float c = 0.f;                                          // log-scale correction

        float e  = EE[NCLS + j];
        int   mv = mS[1];

        for (int t = 1; t < SEQ; ++t) {
            float e_nxt = 0.f; int m_nxt = 0;
            if (t < SEQ - 1) { e_nxt = EE[(t + 1) * NCLS + j]; m_nxt = mS[t + 1]; }

            const float p0 = __shfl_sync(0xffffffffu, p, 0);
            const float p1 = __shfl_sync(0xffffffffu, p, 1);
            const float p2 = __shfl_sync(0xffffffffu, p, 2);
            const float p3 = __shfl_sync(0xffffffffu, p, 3);
            const float p4 = __shfl_sync(0xffffffffu, p, 4);
            const float p5 = __shfl_sync(0xffffffffu, p, 5);
            const float p6 = __shfl_sync(0xffffffffu, p, 6);
            const float p7 = __shfl_sync(0xffffffffu, p, 7);
            const float p8 = __shfl_sync(0xffffffffu, p, 8);

            const float s0 = fmaf(p2, trM[2], fmaf(p1, trM[1], p0 * trM[0]));
            const float s1 = fmaf(p5, trM[5], fmaf(p4, trM[4], p3 * trM[3]));
            const float s2 = fmaf(p8, trM[8], fmaf(p7, trM[7], p6 * trM[6]));
            const float pn = ((s0 + s1) + s2) * e;

            p = mv ? pn : p;

            if ((t & 7) == 7) {
                // renormalize: divide by warp max, fold into log correction
                float m = p;
#pragma unroll
                for (int off = 16; off; off >>= 1)
                    m = fmaxf(m, __shfl_xor_sync(0xffffffffu, m, off));
                c += logf(m);
                p = p / m;
            }
            e = e_nxt; mv = m_nxt;
        }

        float v = (lane < NCLS) ? p * expf(enS[j]) : 0.f;
#pragma unroll
        for (int off = 16; off; off >>= 1)
            v += __shfl_xor_sync(0xffffffffu, v, off);
        if (lane == 0) den_sh = c + logf(v);
    }
    else if (warp == 1) {
        float sc = 0.f;
        int   cnt = 0;
        for (int t = lane; t < SEQ; t += 32) {
            const int mt = mS[t];
            cnt += mt;
            if (t >= 1 && mt) {
                const int cur = tagS[t];
                const int prv = tagS[t - 1];
                sc += LG[t * NCLS + cur] + trS[prv * NCLS + cur];
            }
        }
#pragma unroll
        for (int off = 16; off; off >>= 1) {
            sc  += __shfl_xor_sync(0xffffffffu, sc,  off);
            cnt += __shfl_xor_sync(0xffffffffu, cnt, off);
        }
        if (lane == 0) {
            const int first = tagS[0];
            sc += stS[first] + LG[first];
            const int se = cnt - 1;          // seq_ends
            sc += enS[tagS[se]];
            num_sh = sc;
        }
    }

    __syncthreads();
    if (tid == 0) g_llh[b] = num_sh - den_sh;
}

// ---------------------------------------------------------------------------
// Kernel 3: loss = -mean(llh), deterministic tree reduction.
// ---------------------------------------------------------------------------
__global__ __launch_bounds__(128) void finalize_kernel(float* __restrict__ out)
{
    __shared__ float ws[4];
    const int tid  = threadIdx.x;
    const int lane = tid & 31;
    const int warp = tid >> 5;

    float v = g_llh[tid];
#pragma unroll
    for (int off = 16; off; off >>= 1)
        v += __shfl_xor_sync(0xffffffffu, v, off);
    if (lane == 0) ws[warp] = v;
    __syncthreads();
    if (tid == 0) {
        const float tot = (ws[0] + ws[1]) + (ws[2] + ws[3]);
        out[0] = -tot / (float)BATCH;
    }
}

// ---------------------------------------------------------------------------
// Launch: inputs in metadata order:
// 0 features f32 [B,S,D], 1 labels i32 [B,S], 2 mask int32(bool) [B,S],
// 3 W f32 [N,D], 4 b f32 [N], 5 start_t f32 [N], 6 end_t f32 [N],
// 7 transitions f32 [N,N].
// Output: [loss (1 float), logits (B*S*N floats)].
// ---------------------------------------------------------------------------
extern "C" void kernel_launch(void* const* d_in, const int* in_sizes, int n_in,
                              void* d_out, int out_size)
{
    const float4* feat4  = (const float4*)d_in[0];
    const int*    labels = (const int*)d_in[1];
    const int*    mask   = (const int*)d_in[2];
    const float*  W      = (const float*)d_in[3];
    const float*  bias   = (const float*)d_in[4];
    const float*  st     = (const float*)d_in[5];
    const float*  en     = (const float*)d_in[6];
    const float*  tr     = (const float*)d_in[7];

    float* out    = (float*)d_out;
    float* logits = out + 1;

    gemm_kernel<<<ROWS / 64, 256>>>(feat4, W, bias, logits);
    crf_kernel<<<BATCH, 128>>>(logits, labels, mask, st, en, tr);
    finalize_kernel<<<1, 128>>>(out);
}

// round 5
// speedup vs baseline: 1.3312x; 1.3312x over previous
#include <cuda_runtime.h>
#include <math.h>
#include <stdint.h>

#define BATCH 128
#define SEQ   512
#define DIM   768
#define NCLS  9
#define ROWS  (BATCH * SEQ)   // 65536
#define D4    (DIM / 4)       // 192
#define NCHUNK 64             // 8 steps per chunk, covers t=1..512 (t=512 padded)

__device__ float g_llh[BATCH];

// ---------------------------------------------------------------------------
// Kernel 1: logits = features @ W^T + b
// 256 threads (8 warps). Warp handles 16 rows: 4 groups x 4 rows, 8 lanes per
// group split D. Each W LDS.128 now feeds 4 rows (was 2) -> half the smem
// wavefront traffic; 4 independent LDGs/iter raises MLP.
// ---------------------------------------------------------------------------
__global__ __launch_bounds__(256) void gemm_kernel(
    const float4* __restrict__ feat4,
    const float*  __restrict__ W,
    const float*  __restrict__ bias,
    float*        __restrict__ out_logits)
{
    __shared__ float4 Ws4[NCLS * D4];  // 27648 B
    __shared__ float  bS[NCLS];

    const float4* W4 = reinterpret_cast<const float4*>(W);
    for (int i = threadIdx.x; i < NCLS * D4; i += 256) Ws4[i] = W4[i];
    if (threadIdx.x < NCLS) bS[threadIdx.x] = bias[threadIdx.x];
    __syncthreads();

    const int warp = threadIdx.x >> 5;
    const int lane = threadIdx.x & 31;
    const int li   = lane & 7;   // d-chunk within group
    const int g    = lane >> 3;  // group (0..3), 4 rows each

    const int row0 = blockIdx.x * 128 + warp * 16 + g * 4;

    float acc[NCLS][4];
#pragma unroll
    for (int n = 0; n < NCLS; ++n)
#pragma unroll
        for (int r = 0; r < 4; ++r) acc[n][r] = 0.f;

    const float4* f0 = feat4 + (size_t)(row0 + 0) * D4;
    const float4* f1 = feat4 + (size_t)(row0 + 1) * D4;
    const float4* f2 = feat4 + (size_t)(row0 + 2) * D4;
    const float4* f3 = feat4 + (size_t)(row0 + 3) * D4;

#pragma unroll 2
    for (int k = 0; k < 24; ++k) {
        const int idx = k * 8 + li;          // 0..191
        const float4 a0 = f0[idx];
        const float4 a1 = f1[idx];
        const float4 a2 = f2[idx];
        const float4 a3 = f3[idx];
#pragma unroll
        for (int n = 0; n < NCLS; ++n) {
            const float4 w = Ws4[n * D4 + idx];
            acc[n][0] = fmaf(a0.x, w.x, fmaf(a0.y, w.y, fmaf(a0.z, w.z, fmaf(a0.w, w.w, acc[n][0]))));
            acc[n][1] = fmaf(a1.x, w.x, fmaf(a1.y, w.y, fmaf(a1.z, w.z, fmaf(a1.w, w.w, acc[n][1]))));
            acc[n][2] = fmaf(a2.x, w.x, fmaf(a2.y, w.y, fmaf(a2.z, w.z, fmaf(a2.w, w.w, acc[n][2]))));
            acc[n][3] = fmaf(a3.x, w.x, fmaf(a3.y, w.y, fmaf(a3.z, w.z, fmaf(a3.w, w.w, acc[n][3]))));
        }
    }

    // reduce over the 8 lanes of each group
#pragma unroll
    for (int n = 0; n < NCLS; ++n)
#pragma unroll
        for (int r = 0; r < 4; ++r)
#pragma unroll
            for (int off = 4; off; off >>= 1)
                acc[n][r] += __shfl_down_sync(0xffffffffu, acc[n][r], off, 8);

    if (li == 0) {
#pragma unroll
        for (int r = 0; r < 4; ++r)
#pragma unroll
            for (int n = 0; n < NCLS; ++n)
                out_logits[(size_t)(row0 + r) * NCLS + n] = acc[n][r] + bS[n];
    }
}

// ---------------------------------------------------------------------------
// Kernel 2: CRF NLL per batch. One 256-thread block per batch element.
// Phase A: stage EE=exp(logits), tags, mask, exp(trans) tables.
// Phase B: build 64 8-step transfer matrices B8[c] = A_{8c+1}..A_{8c+8}
//          (A_t = Mexp*diag(e_t); identity when masked) via 576 column tasks.
// Phase C: warp0 runs the 64-step serial scan p^T <- p^T B8[c];
//          warp1 computes the gold-path numerator concurrently.
// ---------------------------------------------------------------------------
__global__ __launch_bounds__(256) void crf_kernel(
    const float* __restrict__ logits,
    const int*   __restrict__ labels,
    const int*   __restrict__ mask,
    const float* __restrict__ start_t,
    const float* __restrict__ end_t,
    const float* __restrict__ trans)
{
    __shared__ float EE[SEQ * NCLS];          // 18432 B  exp(logits)
    __shared__ float B8[NCHUNK * 81];         // 20736 B  transfer matrices [c][i][j]
    __shared__ float trT[NCLS * 12];          // 432 B    exp(trans) transposed, padded rows
    __shared__ float trS[NCLS * NCLS];        // 324 B    raw trans (numerator)
    __shared__ int   tagS[SEQ];               // 2048 B
    __shared__ int   mS[SEQ + 1];             // 2052 B
    __shared__ float stS[NCLS], enS[NCLS];
    __shared__ float num_sh, den_sh;

    const int b   = blockIdx.x;
    const int tid = threadIdx.x;
    const float* lgb = logits + (size_t)b * SEQ * NCLS;

    // ---- Phase A: staging ----
    for (int i = tid; i < SEQ * NCLS; i += 256)
        EE[i] = __expf(lgb[i]);
    for (int i = tid; i < SEQ; i += 256) {
        const int lab = labels[(size_t)b * SEQ + i];
        tagS[i] = (lab == -100) ? 0 : lab;
        mS[i]   = (mask[(size_t)b * SEQ + i] != 0) ? 1 : 0;
    }
    if (tid == 0) mS[SEQ] = 0;                // pad step t=512
    if (tid < NCLS * NCLS) {
        const float tv = trans[tid];
        trS[tid] = tv;
        const int i = tid / NCLS, k = tid % NCLS;
        trT[k * 12 + i] = __expf(tv);         // trT[k][i] = exp(trans[i][k])
    }
    if (tid < NCLS) { stS[tid] = start_t[tid]; enS[tid] = end_t[tid]; }
    __syncthreads();

    // ---- Phase B: build B8 (576 column tasks) ----
    for (int task = tid; task < NCHUNK * NCLS; task += 256) {
        const int c = task / NCLS;
        const int j = task - c * NCLS;
        float v[NCLS];
#pragma unroll
        for (int i = 0; i < NCLS; ++i) v[i] = (i == j) ? 1.f : 0.f;

        // right-to-left: v = A_{t1} (... (A_{t8} e_j))
        for (int s = 7; s >= 0; --s) {
            const int t = 8 * c + 1 + s;       // 1..512
            if (mS[t]) {
                const float* eT = &EE[t * NCLS];
                float4 va = make_float4(0.f, 0.f, 0.f, 0.f);
                float4 vb = make_float4(0.f, 0.f, 0.f, 0.f);
                float  v8 = 0.f;
#pragma unroll
                for (int k = 0; k < NCLS; ++k) {
                    const float u = eT[k] * v[k];
                    const float4 t0 = *reinterpret_cast<const float4*>(&trT[k * 12 + 0]);
                    const float4 t1 = *reinterpret_cast<const float4*>(&trT[k * 12 + 4]);
                    const float  t2 = trT[k * 12 + 8];
                    va.x = fmaf(t0.x, u, va.x); va.y = fmaf(t0.y, u, va.y);
                    va.z = fmaf(t0.z, u, va.z); va.w = fmaf(t0.w, u, va.w);
                    vb.x = fmaf(t1.x, u, vb.x); vb.y = fmaf(t1.y, u, vb.y);
                    vb.z = fmaf(t1.z, u, vb.z); vb.w = fmaf(t1.w, u, vb.w);
                    v8   = fmaf(t2,   u, v8);
                }
                v[0] = va.x; v[1] = va.y; v[2] = va.z; v[3] = va.w;
                v[4] = vb.x; v[5] = vb.y; v[6] = vb.z; v[7] = vb.w;
                v[8] = v8;
            }
        }
#pragma unroll
        for (int i = 0; i < NCLS; ++i)
            B8[c * 81 + i * NCLS + j] = v[i];
    }
    __syncthreads();

    // ---- Phase C ----
    const int warp = tid >> 5;
    const int lane = tid & 31;

    if (warp == 0) {
        const int j = (lane < NCLS) ? lane : 0;
        float p = (lane < NCLS) ? __expf(stS[j] + lgb[j]) : 0.f;
        float clog = 0.f;

        // prefetch chunk 0 column
        float bcol[NCLS];
#pragma unroll
        for (int i = 0; i < NCLS; ++i) bcol[i] = B8[i * NCLS + j];

        for (int ch = 0; ch < NCHUNK; ++ch) {
            float nb[NCLS];
            if (ch < NCHUNK - 1) {
                const float* base = &B8[(ch + 1) * 81 + j];
#pragma unroll
                for (int i = 0; i < NCLS; ++i) nb[i] = base[i * NCLS];
            }

            const float p0 = __shfl_sync(0xffffffffu, p, 0);
            const float p1 = __shfl_sync(0xffffffffu, p, 1);
            const float p2 = __shfl_sync(0xffffffffu, p, 2);
            const float p3 = __shfl_sync(0xffffffffu, p, 3);
            const float p4 = __shfl_sync(0xffffffffu, p, 4);
            const float p5 = __shfl_sync(0xffffffffu, p, 5);
            const float p6 = __shfl_sync(0xffffffffu, p, 6);
            const float p7 = __shfl_sync(0xffffffffu, p, 7);
            const float p8 = __shfl_sync(0xffffffffu, p, 8);

            const float s0 = fmaf(p2, bcol[2], fmaf(p1, bcol[1], p0 * bcol[0]));
            const float s1 = fmaf(p5, bcol[5], fmaf(p4, bcol[4], p3 * bcol[3]));
            const float s2 = fmaf(p8, bcol[8], fmaf(p7, bcol[7], p6 * bcol[6]));
            float pn = (s0 + s1) + s2;

            if (ch & 1) {
                // renormalize by lane-0 value (always > 0); fold into clog
                const float s = __shfl_sync(0xffffffffu, pn, 0);
                pn *= __frcp_rn(s);
                clog += __logf(s);
            }
            p = pn;
#pragma unroll
            for (int i = 0; i < NCLS; ++i) bcol[i] = nb[i];
        }

        float v = (lane < NCLS) ? p * __expf(enS[j]) : 0.f;
#pragma unroll
        for (int off = 16; off; off >>= 1)
            v += __shfl_xor_sync(0xffffffffu, v, off);
        if (lane == 0) den_sh = clog + __logf(v);
    }
    else if (warp == 1) {
        float sc = 0.f;
        int   cnt = 0;
        for (int t = lane; t < SEQ; t += 32) {
            const int mt = mS[t];
            cnt += mt;
            if (t >= 1 && mt) {
                const int cur = tagS[t];
                const int prv = tagS[t - 1];
                sc += lgb[t * NCLS + cur] + trS[prv * NCLS + cur];
            }
        }
#pragma unroll
        for (int off = 16; off; off >>= 1) {
            sc  += __shfl_xor_sync(0xffffffffu, sc,  off);
            cnt += __shfl_xor_sync(0xffffffffu, cnt, off);
        }
        if (lane == 0) {
            const int first = tagS[0];
            sc += stS[first] + lgb[first];
            sc += enS[tagS[cnt - 1]];
            num_sh = sc;
        }
    }

    __syncthreads();
    if (tid == 0) g_llh[b] = num_sh - den_sh;
}

// ---------------------------------------------------------------------------
// Kernel 3: loss = -mean(llh), deterministic tree reduction.
// ---------------------------------------------------------------------------
__global__ __launch_bounds__(128) void finalize_kernel(float* __restrict__ out)
{
    __shared__ float ws[4];
    const int tid  = threadIdx.x;
    const int lane = tid & 31;
    const int warp = tid >> 5;

    float v = g_llh[tid];
#pragma unroll
    for (int off = 16; off; off >>= 1)
        v += __shfl_xor_sync(0xffffffffu, v, off);
    if (lane == 0) ws[warp] = v;
    __syncthreads();
    if (tid == 0) {
        const float tot = (ws[0] + ws[1]) + (ws[2] + ws[3]);
        out[0] = -tot / (float)BATCH;
    }
}

extern "C" void kernel_launch(void* const* d_in, const int* in_sizes, int n_in,
                              void* d_out, int out_size)
{
    const float4* feat4  = (const float4*)d_in[0];
    const int*    labels = (const int*)d_in[1];
    const int*    mask   = (const int*)d_in[2];
    const float*  W      = (const float*)d_in[3];
    const float*  bias   = (const float*)d_in[4];
    const float*  st     = (const float*)d_in[5];
    const float*  en     = (const float*)d_in[6];
    const float*  tr     = (const float*)d_in[7];

    float* out    = (float*)d_out;
    float* logits = out + 1;

    gemm_kernel<<<ROWS / 128, 256>>>(feat4, W, bias, logits);
    crf_kernel<<<BATCH, 256>>>(logits, labels, mask, st, en, tr);
    finalize_kernel<<<1, 128>>>(out);
}